// round 2
// baseline (speedup 1.0000x reference)
#include <cuda_runtime.h>
#include <math.h>

// Problem dims (fixed by the dataset)
#define NBATCH 128
#define NI     2048
#define DI     16
#define NO     32
#define DO     16

#define NCHUNK 128                // i-chunks
#define ICHUNK (NI / NCHUNK)      // 16 i per CTA
#define JD     (NO * DO)          // 512

// pass 1 tiling
#define BG1    16
#define NBG1   (NBATCH / BG1)     // 8
// pass 2 tiling (smaller to keep regs < 128)
#define BG2    8
#define NBG2   (NBATCH / BG2)     // 16

// Deterministic partial buffers (no atomics anywhere).
__device__ float g_S0part[(size_t)NCHUNK * NBATCH * JD];   // 33.5 MB
__device__ float g_S1part[(size_t)NCHUNK * NBATCH * JD];   // 33.5 MB
__device__ float g_V0[NBATCH * JD];

// ---------------------------------------------------------------------------
// helpers
// ---------------------------------------------------------------------------
__device__ __forceinline__ void load_w_rows(const float* __restrict__ W,
                                            int i, int j, int d0,
                                            float (&w0)[16], float (&w1)[16])
{
    const float4* Wp = reinterpret_cast<const float4*>(
        W + (((size_t)i * NO + j) * DO + d0) * DI);
#pragma unroll
    for (int q = 0; q < 4; ++q) {
        float4 a = Wp[q];
        w0[q*4+0] = a.x; w0[q*4+1] = a.y; w0[q*4+2] = a.z; w0[q*4+3] = a.w;
        float4 b = Wp[4+q];
        w1[q*4+0] = b.x; w1[q*4+1] = b.y; w1[q*4+2] = b.z; w1[q*4+3] = b.w;
    }
}

// stage X[bg*BGN .. +BGN][i0 .. i0+ICHUNK][0..15] into smem
template<int BGN>
__device__ __forceinline__ void stage_x(float4* Xs4, const float* __restrict__ X,
                                        int bg, int i0, int t)
{
    const float4* Xg = reinterpret_cast<const float4*>(X);
    const int TOT = BGN * ICHUNK * (DI/4);   // float4 count
#pragma unroll
    for (int r = 0; r < TOT / 256; ++r) {
        int e   = t + r * 256;
        int bb  = e >> 6;              // ICHUNK*DI/4 = 64 float4 per batch
        int off = e & 63;
        Xs4[e] = Xg[(size_t)(bg*BGN + bb) * (NI*DI/4) + (size_t)i0 * (DI/4) + off];
    }
}

// ---------------------------------------------------------------------------
// Pass 1: S0part[chunk][b][j][d] = sum_{i in chunk} X_hat[b,i,j,d]
// grid (NBG1, NCHUNK), block 256. thread = (j = t>>3, dpair = t&7)
// ---------------------------------------------------------------------------
__global__ __launch_bounds__(256, 2)
void caps_pass1(const float* __restrict__ X, const float* __restrict__ W)
{
    __shared__ float4 Xs4[BG1 * ICHUNK * (DI/4)];   // 16 KB

    const int bg    = blockIdx.x;
    const int chunk = blockIdx.y;
    const int i0    = chunk * ICHUNK;
    const int t     = threadIdx.x;
    const int j     = t >> 3;
    const int d0    = (t & 7) * 2;

    stage_x<BG1>(Xs4, X, bg, i0, t);
    __syncthreads();

    float acc0[BG1], acc1[BG1];
#pragma unroll
    for (int b = 0; b < BG1; ++b) { acc0[b] = 0.f; acc1[b] = 0.f; }

    for (int ii = 0; ii < ICHUNK; ++ii) {
        float w0[16], w1[16];
        load_w_rows(W, i0 + ii, j, d0, w0, w1);
#pragma unroll
        for (int b = 0; b < BG1; ++b) {
            float a0 = acc0[b], a1 = acc1[b];
#pragma unroll
            for (int q = 0; q < 4; ++q) {
                float4 xv = Xs4[b * (ICHUNK*(DI/4)) + ii * (DI/4) + q];
                a0 = fmaf(w0[q*4+0], xv.x, a0); a1 = fmaf(w1[q*4+0], xv.x, a1);
                a0 = fmaf(w0[q*4+1], xv.y, a0); a1 = fmaf(w1[q*4+1], xv.y, a1);
                a0 = fmaf(w0[q*4+2], xv.z, a0); a1 = fmaf(w1[q*4+2], xv.z, a1);
                a0 = fmaf(w0[q*4+3], xv.w, a0); a1 = fmaf(w1[q*4+3], xv.w, a1);
            }
            acc0[b] = a0; acc1[b] = a1;
        }
    }

    float2* out = reinterpret_cast<float2*>(g_S0part + (size_t)chunk * NBATCH * JD);
#pragma unroll
    for (int b = 0; b < BG1; ++b) {
        int gb = bg * BG1 + b;
        out[gb * (JD/2) + j * (DO/2) + (d0 >> 1)] = make_float2(acc0[b], acc1[b]);
    }
}

// ---------------------------------------------------------------------------
// Reduce S0 partials + squash -> g_V0.  4096 threads, one per (b, j).
// ---------------------------------------------------------------------------
__global__ void caps_squash_v0()
{
    int t = blockIdx.x * blockDim.x + threadIdx.x;
    int b = t >> 5, j = t & 31;
    float s[DO];
#pragma unroll
    for (int d = 0; d < DO; ++d) s[d] = 0.f;
    const float4* P = reinterpret_cast<const float4*>(g_S0part);
    size_t base = ((size_t)b * JD + (size_t)j * DO) >> 2;
    for (int c = 0; c < NCHUNK; ++c) {
        const float4* p = P + (size_t)c * (NBATCH*JD/4) + base;
#pragma unroll
        for (int q = 0; q < 4; ++q) {
            float4 v = p[q];
            s[q*4+0] += v.x; s[q*4+1] += v.y; s[q*4+2] += v.z; s[q*4+3] += v.w;
        }
    }
    float n2 = 0.f;
#pragma unroll
    for (int d = 0; d < DO; ++d) { s[d] *= (1.0f / NO); n2 = fmaf(s[d], s[d], n2); }
    float f = sqrtf(n2) / (1.0f + n2);
    float4* V = reinterpret_cast<float4*>(g_V0);
#pragma unroll
    for (int q = 0; q < 4; ++q)
        V[base + q] = make_float4(s[q*4+0]*f, s[q*4+1]*f, s[q*4+2]*f, s[q*4+3]*f);
}

// ---------------------------------------------------------------------------
// Pass 2 (fused): X_hat -> b1 -> softmax_j -> S1 partial accumulate.
// grid (NBG2, NCHUNK), block 256. thread = (j, dpair) as pass 1, BG2=8.
// V0 slice lives in registers (each thread reads a fixed (j,d0) across b).
// ---------------------------------------------------------------------------
__global__ __launch_bounds__(256, 2)
void caps_pass2(const float* __restrict__ X, const float* __restrict__ W)
{
    __shared__ float4 Xs4[BG2 * ICHUNK * (DI/4)];   // 8 KB
    __shared__ float  Csm[BG2 * NO];                // 1 KB (b1, then c)

    const int bg    = blockIdx.x;
    const int chunk = blockIdx.y;
    const int i0    = chunk * ICHUNK;
    const int t     = threadIdx.x;
    const int j     = t >> 3;
    const int d0    = (t & 7) * 2;
    const int wz    = t >> 5;
    const int lane  = t & 31;

    stage_x<BG2>(Xs4, X, bg, i0, t);

    // V0 values for this thread's (j, d-pair) across its BG2 batches
    float2 vreg[BG2];
#pragma unroll
    for (int b = 0; b < BG2; ++b)
        vreg[b] = *reinterpret_cast<const float2*>(
            &g_V0[(size_t)(bg * BG2 + b) * JD + j * DO + d0]);

    __syncthreads();

    float s1a[BG2], s1b[BG2];
#pragma unroll
    for (int b = 0; b < BG2; ++b) { s1a[b] = 0.f; s1b[b] = 0.f; }

    for (int ii = 0; ii < ICHUNK; ++ii) {
        float w0[16], w1[16];
        load_w_rows(W, i0 + ii, j, d0, w0, w1);

        float xh0[BG2], xh1[BG2];
#pragma unroll
        for (int b = 0; b < BG2; ++b) {
            float a0 = 0.f, a1 = 0.f;
#pragma unroll
            for (int q = 0; q < 4; ++q) {
                float4 xv = Xs4[b * (ICHUNK*(DI/4)) + ii * (DI/4) + q];
                a0 = fmaf(w0[q*4+0], xv.x, a0); a1 = fmaf(w1[q*4+0], xv.x, a1);
                a0 = fmaf(w0[q*4+1], xv.y, a0); a1 = fmaf(w1[q*4+1], xv.y, a1);
                a0 = fmaf(w0[q*4+2], xv.z, a0); a1 = fmaf(w1[q*4+2], xv.z, a1);
                a0 = fmaf(w0[q*4+3], xv.w, a0); a1 = fmaf(w1[q*4+3], xv.w, a1);
            }
            xh0[b] = a0; xh1[b] = a1;
        }

        // b1 partial over this thread's d-pair, then reduce across 8 dpair lanes
        float p[BG2];
#pragma unroll
        for (int b = 0; b < BG2; ++b)
            p[b] = xh0[b] * vreg[b].x + xh1[b] * vreg[b].y;
#pragma unroll
        for (int off = 1; off < 8; off <<= 1)
#pragma unroll
            for (int b = 0; b < BG2; ++b)
                p[b] += __shfl_xor_sync(0xffffffffu, p[b], off);

        __syncthreads();                 // prior iteration done reading Csm
        if ((t & 7) == 0) {
#pragma unroll
            for (int b = 0; b < BG2; ++b) Csm[b * NO + j] = p[b];
        }
        __syncthreads();

        // softmax over j: warp wz handles batch row wz (8 warps, BG2=8 rows)
        {
            int b = wz;
            float v = Csm[b * NO + lane];
            float m = v;
#pragma unroll
            for (int off = 16; off; off >>= 1)
                m = fmaxf(m, __shfl_xor_sync(0xffffffffu, m, off));
            float e = __expf(v - m);
            float ss = e;
#pragma unroll
            for (int off = 16; off; off >>= 1)
                ss += __shfl_xor_sync(0xffffffffu, ss, off);
            Csm[b * NO + lane] = e / ss;
        }
        __syncthreads();

#pragma unroll
        for (int b = 0; b < BG2; ++b) {
            float c = Csm[b * NO + j];
            s1a[b] = fmaf(c, xh0[b], s1a[b]);
            s1b[b] = fmaf(c, xh1[b], s1b[b]);
        }
    }

    float2* out = reinterpret_cast<float2*>(g_S1part + (size_t)chunk * NBATCH * JD);
#pragma unroll
    for (int b = 0; b < BG2; ++b) {
        int gb = bg * BG2 + b;
        out[gb * (JD/2) + j * (DO/2) + (d0 >> 1)] = make_float2(s1a[b], s1b[b]);
    }
}

// ---------------------------------------------------------------------------
// Reduce S1 partials + squash -> output
// ---------------------------------------------------------------------------
__global__ void caps_squash_out(float* __restrict__ out)
{
    int t = blockIdx.x * blockDim.x + threadIdx.x;
    int b = t >> 5, j = t & 31;
    float s[DO];
#pragma unroll
    for (int d = 0; d < DO; ++d) s[d] = 0.f;
    const float4* P = reinterpret_cast<const float4*>(g_S1part);
    size_t base = ((size_t)b * JD + (size_t)j * DO) >> 2;
    for (int c = 0; c < NCHUNK; ++c) {
        const float4* p = P + (size_t)c * (NBATCH*JD/4) + base;
#pragma unroll
        for (int q = 0; q < 4; ++q) {
            float4 v = p[q];
            s[q*4+0] += v.x; s[q*4+1] += v.y; s[q*4+2] += v.z; s[q*4+3] += v.w;
        }
    }
    float n2 = 0.f;
#pragma unroll
    for (int d = 0; d < DO; ++d) n2 = fmaf(s[d], s[d], n2);
    float f = sqrtf(n2) / (1.0f + n2);
    float4* O = reinterpret_cast<float4*>(out);
#pragma unroll
    for (int q = 0; q < 4; ++q)
        O[base + q] = make_float4(s[q*4+0]*f, s[q*4+1]*f, s[q*4+2]*f, s[q*4+3]*f);
}

// ---------------------------------------------------------------------------
extern "C" void kernel_launch(void* const* d_in, const int* in_sizes, int n_in,
                              void* d_out, int out_size)
{
    const float* X = (const float*)d_in[0];
    const float* W = (const float*)d_in[1];
    // defensive: identify by size (X = 4,194,304 ; W = 16,777,216)
    if (n_in >= 2 && in_sizes[0] == NI * NO * DO * DI && in_sizes[1] == NBATCH * NI * DI) {
        W = (const float*)d_in[0];
        X = (const float*)d_in[1];
    }

    dim3 grid1(NBG1, NCHUNK);  // x fast -> same-chunk CTAs co-resident for W L2 reuse
    dim3 grid2(NBG2, NCHUNK);
    caps_pass1<<<grid1, 256>>>(X, W);
    caps_squash_v0<<<16, 256>>>();
    caps_pass2<<<grid2, 256>>>(X, W);
    caps_squash_out<<<16, 256>>>((float*)d_out);
}